// round 9
// baseline (speedup 1.0000x reference)
#include <cuda_runtime.h>
#include <cuda_bf16.h>
#include <cstdint>

#define Bn 128
#define Sn 256
#define Hn 1024
#define Tn 20
#define G4n 4096
#define DTn 1044
#define START_I 19
#define NBLK 128u

typedef unsigned long long u64t;

// ---------------- device scratch ----------------
__device__ float g_G[(size_t)Sn * Bn * G4n];                 // x-projection + biases (fp32)
__device__ float g_h[2][Bn * Hn];                            // fp32 h (for logits)
__device__ float g_Wtag[Tn * G4n];                           // one-hot columns of W_ih
__device__ __align__(16) uint4 g_Bq[1048576];                // Whh B-frags interleaved {bh0,bh1,bl0,bl1} (16MB)
__device__ __align__(16) uint32_t g_hAh[2][65536];           // h bf16-hi A-frags (ping-pong)
__device__ __align__(16) uint32_t g_hAl[2][65536];           // h bf16-lo residual
__device__ __align__(16) uint4 g_xh[4194304];                // x bf16-hi A-frags (67MB)
__device__ __align__(16) uint4 g_xl[4194304];                // x bf16-lo A-frags (67MB)
__device__ __align__(16) uint2 g_wfh[1048576];               // W_ih bf16-hi B-frags (8MB)
__device__ __align__(16) uint2 g_wfl[1048576];               // W_ih bf16-lo B-frags (8MB)
__device__ int   g_ptag[Bn];
__device__ double g_loss;
__device__ unsigned g_bar_arrive, g_bar_phase, g_ptag_ready;

// ---------------- HMMA bf16 ----------------
__device__ __forceinline__ void mma_bf16(float* d,
    uint32_t a0, uint32_t a1, uint32_t a2, uint32_t a3,
    uint32_t b0, uint32_t b1)
{
    asm volatile(
        "mma.sync.aligned.m16n8k16.row.col.f32.bf16.bf16.f32 "
        "{%0,%1,%2,%3}, {%4,%5,%6,%7}, {%8,%9}, {%0,%1,%2,%3};"
        : "+f"(d[0]), "+f"(d[1]), "+f"(d[2]), "+f"(d[3])
        : "r"(a0), "r"(a1), "r"(a2), "r"(a3), "r"(b0), "r"(b1));
}
__device__ __forceinline__ uint32_t pack_bf16_hi(float x, float y) {
    __nv_bfloat16 bx = __float2bfloat16(x), by = __float2bfloat16(y);
    return (uint32_t)__bfloat16_as_ushort(bx) | ((uint32_t)__bfloat16_as_ushort(by) << 16);
}
__device__ __forceinline__ uint32_t pack_bf16_lo(float x, float y) {
    __nv_bfloat16 bx = __float2bfloat16(x), by = __float2bfloat16(y);
    float rx = x - __bfloat162float(bx), ry = y - __bfloat162float(by);
    __nv_bfloat16 lx = __float2bfloat16(rx), ly = __float2bfloat16(ry);
    return (uint32_t)__bfloat16_as_ushort(lx) | ((uint32_t)__bfloat16_as_ushort(ly) << 16);
}

// ---------------- software grid barrier ----------------
__device__ __forceinline__ void grid_bar() {
    __syncthreads();
    if (threadIdx.x == 0) {
        unsigned gen = *(volatile unsigned*)&g_bar_phase;
        __threadfence();
        unsigned t = atomicAdd(&g_bar_arrive, 1u);
        if (t == NBLK - 1u) {
            *(volatile unsigned*)&g_bar_arrive = 0u;
            __threadfence();
            *(volatile unsigned*)&g_bar_phase = gen + 1u;
        } else {
            while (*(volatile unsigned*)&g_bar_phase == gen) {}
            __threadfence();
        }
    }
    __syncthreads();
}

// ---------------- init: misc + Whh B-frags (interleaved) + W_ih B-frags ----------------
__global__ void init_kernel(const float* __restrict__ Wih, const float* __restrict__ Whh) {
    int idx = blockIdx.x * blockDim.x + threadIdx.x;   // 0 .. 4194303
    if (idx < Bn) g_ptag[idx] = START_I;
    if (idx == 0) { g_loss = 0.0; g_bar_arrive = 0u; g_ptag_ready = 0u; }
    if (idx < Tn * G4n) {
        int t = idx >> 12;
        int n = idx & (G4n - 1);
        g_Wtag[idx] = Wih[(size_t)n * DTn + Hn + t];
    }
    if (idx < 1048576) {   // Whh B-frags, interleaved hi/lo per uint4
        int lane = idx & 31;
        int kt   = (idx >> 5) & 63;
        int nt   = (idx >> 11) & 3;
        int bid  = idx >> 13;
        int g = lane >> 2, tig = lane & 3;
        int n = nt * 1024 + bid * 8 + g;
        int k0 = kt * 16 + 2 * tig;
        const float* W = Whh + (size_t)n * Hn;
        float v00 = W[k0], v01 = W[k0 + 1], v10 = W[k0 + 8], v11 = W[k0 + 9];
        g_Bq[idx] = make_uint4(pack_bf16_hi(v00, v01), pack_bf16_hi(v10, v11),
                               pack_bf16_lo(v00, v01), pack_bf16_lo(v10, v11));
    }
    if (idx < 1048576) {   // W_ih B-frags (xproj)
        int lane = idx & 31;
        int kt   = (idx >> 5) & 63;
        int nt2  = idx >> 11;
        int g = lane >> 2, tig = lane & 3;
        int n = nt2 * 8 + g;
        int k0 = kt * 16 + 2 * tig;
        const float* W = Wih + (size_t)n * DTn;
        float a = W[k0], b = W[k0 + 1], c = W[k0 + 8], d = W[k0 + 9];
        g_wfh[idx] = make_uint2(pack_bf16_hi(a, b), pack_bf16_hi(c, d));
        g_wfl[idx] = make_uint2(pack_bf16_lo(a, b), pack_bf16_lo(c, d));
    }
}

// ---------------- x -> A-fragment hi/lo bf16 (one-time) ----------------
__global__ void xprep_kernel(const float* __restrict__ x) {
    int idx = blockIdx.x * blockDim.x + threadIdx.x;   // 0 .. 4194303
    int lane = idx & 31;
    int kt = (idx >> 5) & 63;
    int mt = idx >> 11;
    int g = lane >> 2, tig = lane & 3;
    int m0 = mt * 16 + g;
    int m1 = m0 + 8;
    int k0 = kt * 16 + 2 * tig;
    const float* r0 = x + ((size_t)((m0 & 127) * 256 + (m0 >> 7))) * Hn;
    const float* r1 = x + ((size_t)((m1 & 127) * 256 + (m1 >> 7))) * Hn;
    float2 v00 = *(const float2*)(r0 + k0);
    float2 v01 = *(const float2*)(r0 + k0 + 8);
    float2 v10 = *(const float2*)(r1 + k0);
    float2 v11 = *(const float2*)(r1 + k0 + 8);
    g_xh[idx] = make_uint4(pack_bf16_hi(v00.x, v00.y), pack_bf16_hi(v10.x, v10.y),
                           pack_bf16_hi(v01.x, v01.y), pack_bf16_hi(v11.x, v11.y));
    g_xl[idx] = make_uint4(pack_bf16_lo(v00.x, v00.y), pack_bf16_lo(v10.x, v10.y),
                           pack_bf16_lo(v01.x, v01.y), pack_bf16_lo(v11.x, v11.y));
}

// ---------------- phase 1: x-projection via HMMA bf16 3-split ----------------
__global__ __launch_bounds__(256) void xproj_kernel(
    const float* __restrict__ bih, const float* __restrict__ bhh)
{
    const int tid = threadIdx.x;
    const int wid = tid >> 5, lane = tid & 31;
    const int g = lane >> 2, tig = lane & 3;
    const int wm = wid & 1, wn = wid >> 1;
    const int mt0 = blockIdx.y * 8 + wm * 4;
    const int nt0 = blockIdx.x * 16 + wn * 4;

    const uint4* Ah = g_xh + (size_t)mt0 * 2048 + lane;
    const uint4* Al = g_xl + (size_t)mt0 * 2048 + lane;
    const uint2* Bh = g_wfh + (size_t)nt0 * 2048 + lane;
    const uint2* Bl = g_wfl + (size_t)nt0 * 2048 + lane;

    float dacc[4][4][4];
#pragma unroll
    for (int i = 0; i < 4; i++)
#pragma unroll
        for (int j = 0; j < 4; j++)
#pragma unroll
            for (int e = 0; e < 4; e++) dacc[i][j][e] = 0.f;

    uint4 ah[4], al[4]; uint2 bh[4], bl[4];
#pragma unroll
    for (int i = 0; i < 4; i++) { ah[i] = __ldg(Ah + i * 2048); al[i] = __ldg(Al + i * 2048); }
#pragma unroll
    for (int j = 0; j < 4; j++) { bh[j] = __ldg(Bh + j * 2048); bl[j] = __ldg(Bl + j * 2048); }

    for (int kt = 0; kt < 64; kt++) {
        uint4 ahn[4], aln[4]; uint2 bhn[4], bln[4];
        if (kt < 63) {
#pragma unroll
            for (int i = 0; i < 4; i++) {
                ahn[i] = __ldg(Ah + i * 2048 + (kt + 1) * 32);
                aln[i] = __ldg(Al + i * 2048 + (kt + 1) * 32);
            }
#pragma unroll
            for (int j = 0; j < 4; j++) {
                bhn[j] = __ldg(Bh + j * 2048 + (kt + 1) * 32);
                bln[j] = __ldg(Bl + j * 2048 + (kt + 1) * 32);
            }
        }
#pragma unroll
        for (int i = 0; i < 4; i++)
#pragma unroll
            for (int j = 0; j < 4; j++)
                mma_bf16(dacc[i][j], ah[i].x, ah[i].y, ah[i].z, ah[i].w, bh[j].x, bh[j].y);
#pragma unroll
        for (int i = 0; i < 4; i++)
#pragma unroll
            for (int j = 0; j < 4; j++)
                mma_bf16(dacc[i][j], al[i].x, al[i].y, al[i].z, al[i].w, bh[j].x, bh[j].y);
#pragma unroll
        for (int i = 0; i < 4; i++)
#pragma unroll
            for (int j = 0; j < 4; j++)
                mma_bf16(dacc[i][j], ah[i].x, ah[i].y, ah[i].z, ah[i].w, bl[j].x, bl[j].y);
#pragma unroll
        for (int i = 0; i < 4; i++) { ah[i] = ahn[i]; al[i] = aln[i]; }
#pragma unroll
        for (int j = 0; j < 4; j++) { bh[j] = bhn[j]; bl[j] = bln[j]; }
    }

#pragma unroll
    for (int j = 0; j < 4; j++) {
        int n = (nt0 + j) * 8 + 2 * tig;
        float b0 = bih[n] + bhh[n];
        float b1 = bih[n + 1] + bhh[n + 1];
#pragma unroll
        for (int i = 0; i < 4; i++) {
            int m = (mt0 + i) * 16 + g;
            *(float2*)(g_G + (size_t)m * G4n + n) =
                make_float2(dacc[i][j][0] + b0, dacc[i][j][1] + b1);
            *(float2*)(g_G + (size_t)(m + 8) * G4n + n) =
                make_float2(dacc[i][j][2] + b0, dacc[i][j][3] + b1);
        }
    }
}

// ---------------- persistent loop: HMMA, asym split-K + warp-specialized logits ----------------
// smem: [0..1024) red, [1024..132096) Bq frags (uint4), [132096..148480) split-K partials
#define LOOP_SMEM 148480

__global__ __launch_bounds__(512, 1) void loop_kernel(
    const float* __restrict__ Wout, const float* __restrict__ bout,
    const int* __restrict__ tags, const int* __restrict__ mask,
    float* __restrict__ out)
{
    extern __shared__ __align__(16) unsigned char smem[];
    float* red = (float*)smem;
    const uint4* Bq = (const uint4*)(smem + 1024);
    float* red2 = (float*)(smem + 132096);   // [16][256]

    const int bid = blockIdx.x;
    const int tid = threadIdx.x;
    const int wid = tid >> 5;
    const int lane = tid & 31;
    const int g = lane >> 2, tig = lane & 3;
    const int wk = wid >> 3;                // 0: kt 0..35, 1: kt 36..63 (+ logits duty)
    const int wm = wid & 7;
    const int gtid = tid & 255;

    {
        const uint4* src = g_Bq + (size_t)bid * 8192;
        uint4* dst = (uint4*)(smem + 1024);
        for (int u = tid; u < 8192; u += 512) dst[u] = src[u];
    }
    __syncthreads();

    const int b1 = wm * 16 + g;
    const int b2 = b1 + 8;
    const int kkg0 = bid * 8 + 2 * tig;
    const int ktbase = wk ? 36 : 0;
    const int kcnt = wk ? 28 : 36;

    float creg[2][2] = {{0.f, 0.f}, {0.f, 0.f}};
    double lossAcc = 0.0;

    // logits helper for step index ls (reads g_h[(ls&1)^1]); wk1 group only.
    auto do_logits = [&](int ls, bool feed) {
        const float4* h4 = (const float4*)(g_h[(ls & 1) ^ 1] + bid * Hn);
        float4 hvv = __ldcg(h4 + gtid);
        const float4* W4 = (const float4*)Wout;
        float p[Tn];
#pragma unroll
        for (int t = 0; t < Tn; t++) {
            float4 w = __ldg(W4 + t * 256 + gtid);
            p[t] = hvv.x * w.x + hvv.y * w.y + hvv.z * w.z + hvv.w * w.w;
        }
#pragma unroll
        for (int t = 0; t < Tn; t++) {
#pragma unroll
            for (int o = 16; o > 0; o >>= 1)
                p[t] += __shfl_xor_sync(0xffffffffu, p[t], o);
        }
        if (lane == 0) {
#pragma unroll
            for (int t = 0; t < Tn; t++) red[(gtid >> 5) * Tn + t] = p[t];
        }
        asm volatile("bar.sync 1, 256;" ::: "memory");
        if (gtid < 32) {
            float l = -3.402823466e38f;
            if (gtid < Tn) {
                l = bout[gtid];
#pragma unroll
                for (int w = 0; w < 8; w++) l += red[w * Tn + gtid];
            }
            float v = l; int idx = gtid;
#pragma unroll
            for (int o = 16; o > 0; o >>= 1) {
                float v2 = __shfl_xor_sync(0xffffffffu, v, o);
                int   i2 = __shfl_xor_sync(0xffffffffu, idx, o);
                if (v2 > v || (v2 == v && i2 < idx)) { v = v2; idx = i2; }
            }
            if (feed && gtid == 0) g_ptag[bid] = idx;
            if (mask[bid * Sn + ls] != 0) {
                float e = (gtid < Tn) ? expf(l - v) : 0.f;
#pragma unroll
                for (int o = 16; o > 0; o >>= 1)
                    e += __shfl_xor_sync(0xffffffffu, e, o);
                int y = tags[bid * Sn + ls];
                float ly = __shfl_sync(0xffffffffu, l, y);
                if (gtid == 0) lossAcc += (double)(v + logf(e) - ly);
            }
            if (feed && gtid == 0) {
                __threadfence();
                atomicAdd(&g_ptag_ready, 1u);
            }
        }
    };

    for (int s = 0; s < Sn; s++) {
        float2 Gv[2][4];
        if (tid < 256) {
#pragma unroll
            for (int r2 = 0; r2 < 2; r2++) {
                int r = r2 ? b2 : b1;
                const float* Gp = g_G + (size_t)(s * Bn + r) * G4n + kkg0;
#pragma unroll
                for (int nt = 0; nt < 4; nt++)
                    Gv[r2][nt] = __ldcs((const float2*)(Gp + nt * 1024));
            }
        }

        float dacc[4][4];
#pragma unroll
        for (int nt = 0; nt < 4; nt++)
#pragma unroll
            for (int e = 0; e < 4; e++) dacc[nt][e] = 0.f;

        if (s > 0) {
            if (wk == 1) do_logits(s - 1, true);   // off critical path: overlaps wk0 GEMM

            const int par = s & 1;
            const uint4* Ah4 = (const uint4*)g_hAh[par] + (wm * 2048 + ktbase * 32 + lane);
            const uint4* Al4 = (const uint4*)g_hAl[par] + (wm * 2048 + ktbase * 32 + lane);
            uint4 ahs[3], als[3];
#pragma unroll
            for (int d = 0; d < 3; d++) {
                ahs[d] = __ldcg(Ah4 + d * 32);
                als[d] = __ldcg(Al4 + d * 32);
            }
            int sl = 0;
#pragma unroll 3
            for (int ktl = 0; ktl < kcnt; ktl++) {
                uint4 ah = ahs[sl], al = als[sl];
                if (ktl + 3 < kcnt) {
                    ahs[sl] = __ldcg(Ah4 + (ktl + 3) * 32);
                    als[sl] = __ldcg(Al4 + (ktl + 3) * 32);
                }
                if (++sl == 3) sl = 0;
                const int kt = ktbase + ktl;
                uint4 q0 = Bq[(0 * 64 + kt) * 32 + lane];
                uint4 q1 = Bq[(1 * 64 + kt) * 32 + lane];
                uint4 q2 = Bq[(2 * 64 + kt) * 32 + lane];
                uint4 q3 = Bq[(3 * 64 + kt) * 32 + lane];
                mma_bf16(dacc[0], ah.x, ah.y, ah.z, ah.w, q0.x, q0.y);
                mma_bf16(dacc[1], ah.x, ah.y, ah.z, ah.w, q1.x, q1.y);
                mma_bf16(dacc[2], ah.x, ah.y, ah.z, ah.w, q2.x, q2.y);
                mma_bf16(dacc[3], ah.x, ah.y, ah.z, ah.w, q3.x, q3.y);
                mma_bf16(dacc[0], al.x, al.y, al.z, al.w, q0.x, q0.y);
                mma_bf16(dacc[1], al.x, al.y, al.z, al.w, q1.x, q1.y);
                mma_bf16(dacc[2], al.x, al.y, al.z, al.w, q2.x, q2.y);
                mma_bf16(dacc[3], al.x, al.y, al.z, al.w, q3.x, q3.y);
                mma_bf16(dacc[0], ah.x, ah.y, ah.z, ah.w, q0.z, q0.w);
                mma_bf16(dacc[1], ah.x, ah.y, ah.z, ah.w, q1.z, q1.w);
                mma_bf16(dacc[2], ah.x, ah.y, ah.z, ah.w, q2.z, q2.w);
                mma_bf16(dacc[3], ah.x, ah.y, ah.z, ah.w, q3.z, q3.w);
            }
        }

        // split-K: wk1 publishes, threads 0-255 accumulate
        if (wk == 1) {
#pragma unroll
            for (int nt = 0; nt < 4; nt++)
#pragma unroll
                for (int e = 0; e < 4; e++)
                    red2[(nt * 4 + e) * 256 + gtid] = dacc[nt][e];
        }
        __syncthreads();
        if (tid < 256) {
#pragma unroll
            for (int nt = 0; nt < 4; nt++)
#pragma unroll
                for (int e = 0; e < 4; e++)
                    dacc[nt][e] += red2[(nt * 4 + e) * 256 + tid];
        }

        if (s > 0) {
            if (tid == 0) {
                while (*(volatile unsigned*)&g_ptag_ready < (unsigned)s * 128u) {}
            }
            __syncthreads();
        }

        // ---- epilogue (threads 0-255) ----
        const int po = (s & 1) ^ 1;
        if (tid < 256) {
            int pt1 = __ldcg(&g_ptag[b1]);
            int pt2 = __ldcg(&g_ptag[b2]);
            const float* W1 = g_Wtag + pt1 * G4n + kkg0;
            const float* W2 = g_Wtag + pt2 * G4n + kkg0;
#pragma unroll
            for (int r2 = 0; r2 < 2; r2++) {
                int r = r2 ? b2 : b1;
                const float* Wt = r2 ? W2 : W1;
                float h01[2];
#pragma unroll
                for (int e = 0; e < 2; e++) {
                    int de = r2 * 2 + e;
                    float G0 = e ? Gv[r2][0].y : Gv[r2][0].x;
                    float G1 = e ? Gv[r2][1].y : Gv[r2][1].x;
                    float G2 = e ? Gv[r2][2].y : Gv[r2][2].x;
                    float G3 = e ? Gv[r2][3].y : Gv[r2][3].x;
                    float gi = dacc[0][de] + G0 + Wt[e];
                    float gf = dacc[1][de] + G1 + Wt[1024 + e];
                    float gg = dacc[2][de] + G2 + Wt[2048 + e];
                    float go = dacc[3][de] + G3 + Wt[3072 + e];
                    gi = 1.f / (1.f + __expf(-gi));
                    gf = 1.f / (1.f + __expf(-gf));
                    gg = tanhf(gg);
                    go = 1.f / (1.f + __expf(-go));
                    creg[r2][e] = gf * creg[r2][e] + gi * gg;
                    h01[e] = go * tanhf(creg[r2][e]);
                }
                *(float2*)(g_h[po] + r * Hn + kkg0) = make_float2(h01[0], h01[1]);
                int idx = ((r >> 4) * 8192) + ((bid >> 1) * 128)
                        + (((r & 7) * 4 + tig) * 4) + ((r >> 3) & 1) + 2 * (bid & 1);
                g_hAh[po][idx] = pack_bf16_hi(h01[0], h01[1]);
                g_hAl[po][idx] = pack_bf16_lo(h01[0], h01[1]);
            }
        }
        grid_bar();
    }

    // tail: logits for s=255 (loss only; h(255)=g_h[0] visible after last grid_bar)
    if (wk == 1) do_logits(255, false);
    if (tid == 256) atomicAdd(&g_loss, lossAcc);
    grid_bar();
    if (bid == 0 && tid == 0) out[0] = (float)(*(volatile double*)&g_loss);
}

// ---------------- launch ----------------
extern "C" void kernel_launch(void* const* d_in, const int* in_sizes, int n_in,
                              void* d_out, int out_size)
{
    const float *x = nullptr, *Wih = nullptr, *Whh = nullptr;
    const float *bih = nullptr, *bhh = nullptr, *Wout = nullptr, *bout = nullptr;
    const int *tags = nullptr, *maskp = nullptr;
    for (int i = 0; i < n_in; i++) {
        int sz = in_sizes[i];
        const void* p = d_in[i];
        switch (sz) {
            case 33554432: x = (const float*)p; break;
            case 4276224:  Wih = (const float*)p; break;
            case 4194304:  Whh = (const float*)p; break;
            case 4096:     if (!bih) bih = (const float*)p; else bhh = (const float*)p; break;
            case 32768:    if (!tags) tags = (const int*)p; else maskp = (const int*)p; break;
            case 20480:    Wout = (const float*)p; break;
            case 20:       bout = (const float*)p; break;
            default: break;
        }
    }

    cudaFuncSetAttribute(loop_kernel, cudaFuncAttributeMaxDynamicSharedMemorySize, LOOP_SMEM);

    init_kernel<<<16384, 256>>>(Wih, Whh);                               // #1
    xprep_kernel<<<16384, 256>>>(x);                                     // #2
    xproj_kernel<<<dim3(32, 256), 256>>>(bih, bhh);                      // #3
    loop_kernel<<<NBLK, 512, LOOP_SMEM>>>(Wout, bout, tags, maskp, (float*)d_out);  // #4 (profiled)
}

// round 10
// speedup vs baseline: 1.3219x; 1.3219x over previous
#include <cuda_runtime.h>
#include <cuda_bf16.h>
#include <cstdint>

#define Bn 128
#define Sn 256
#define Hn 1024
#define Tn 20
#define G4n 4096
#define DTn 1044
#define START_I 19
#define NBLK 128u

typedef unsigned long long u64t;

// ---------------- device scratch ----------------
__device__ float g_G[(size_t)Sn * Bn * G4n];                 // x-projection + biases (fp32)
__device__ float g_h[2][Bn * Hn];                            // fp32 h (for logits)
__device__ float g_Wtag[Tn * G4n];                           // one-hot columns of W_ih
__device__ __align__(16) u64t g_Bfrag[2097152];              // Whh bf16 hi/lo B-frags (16MB)
__device__ __align__(16) uint32_t g_hAh[2][65536];           // h bf16-hi A-frags (ping-pong)
__device__ __align__(16) uint32_t g_hAl[2][65536];           // h bf16-lo residual
__device__ __align__(16) uint4 g_xh[4194304];                // x bf16-hi A-frags (67MB)
__device__ __align__(16) uint4 g_xl[4194304];                // x bf16-lo A-frags (67MB)
__device__ __align__(16) uint2 g_wfh[1048576];               // W_ih bf16-hi B-frags (8MB)
__device__ __align__(16) uint2 g_wfl[1048576];               // W_ih bf16-lo B-frags (8MB)
__device__ int   g_ptag[Bn];
__device__ double g_loss;
__device__ unsigned g_bar_arrive, g_bar_phase, g_ptag_ready;

// ---------------- HMMA bf16 ----------------
__device__ __forceinline__ void mma_bf16(float* d,
    uint32_t a0, uint32_t a1, uint32_t a2, uint32_t a3,
    uint32_t b0, uint32_t b1)
{
    asm volatile(
        "mma.sync.aligned.m16n8k16.row.col.f32.bf16.bf16.f32 "
        "{%0,%1,%2,%3}, {%4,%5,%6,%7}, {%8,%9}, {%0,%1,%2,%3};"
        : "+f"(d[0]), "+f"(d[1]), "+f"(d[2]), "+f"(d[3])
        : "r"(a0), "r"(a1), "r"(a2), "r"(a3), "r"(b0), "r"(b1));
}
__device__ __forceinline__ uint32_t pack_bf16_hi(float x, float y) {
    __nv_bfloat16 bx = __float2bfloat16(x), by = __float2bfloat16(y);
    return (uint32_t)__bfloat16_as_ushort(bx) | ((uint32_t)__bfloat16_as_ushort(by) << 16);
}
__device__ __forceinline__ uint32_t pack_bf16_lo(float x, float y) {
    __nv_bfloat16 bx = __float2bfloat16(x), by = __float2bfloat16(y);
    float rx = x - __bfloat162float(bx), ry = y - __bfloat162float(by);
    __nv_bfloat16 lx = __float2bfloat16(rx), ly = __float2bfloat16(ry);
    return (uint32_t)__bfloat16_as_ushort(lx) | ((uint32_t)__bfloat16_as_ushort(ly) << 16);
}

// ---------------- software grid barrier ----------------
__device__ __forceinline__ void grid_bar() {
    __syncthreads();
    if (threadIdx.x == 0) {
        unsigned gen = *(volatile unsigned*)&g_bar_phase;
        __threadfence();
        unsigned t = atomicAdd(&g_bar_arrive, 1u);
        if (t == NBLK - 1u) {
            *(volatile unsigned*)&g_bar_arrive = 0u;
            __threadfence();
            *(volatile unsigned*)&g_bar_phase = gen + 1u;
        } else {
            while (*(volatile unsigned*)&g_bar_phase == gen) {}
            __threadfence();
        }
    }
    __syncthreads();
}

// ---------------- init: misc + Whh B-frags + W_ih B-frags ----------------
__global__ void init_kernel(const float* __restrict__ Wih, const float* __restrict__ Whh) {
    int idx = blockIdx.x * blockDim.x + threadIdx.x;   // 0 .. 4194303
    if (idx < Bn) g_ptag[idx] = START_I;
    if (idx == 0) { g_loss = 0.0; g_bar_arrive = 0u; g_ptag_ready = 0u; }
    if (idx < Tn * G4n) {
        int t = idx >> 12;
        int n = idx & (G4n - 1);
        g_Wtag[idx] = Wih[(size_t)n * DTn + Hn + t];
    }
    if (idx < 2097152) {   // Whh B-frags (loop kernel)
        int lane  = idx & 31;
        int kt    = (idx >> 5) & 63;
        int nt    = (idx >> 11) & 3;
        int which = (idx >> 13) & 1;
        int bid   = idx >> 14;
        int g = lane >> 2, tig = lane & 3;
        int n = nt * 1024 + bid * 8 + g;
        int k0 = kt * 16 + 2 * tig;
        const float* W = Whh + (size_t)n * Hn;
        float v00 = W[k0], v01 = W[k0 + 1], v10 = W[k0 + 8], v11 = W[k0 + 9];
        uint32_t r0, r1;
        if (which == 0) { r0 = pack_bf16_hi(v00, v01); r1 = pack_bf16_hi(v10, v11); }
        else            { r0 = pack_bf16_lo(v00, v01); r1 = pack_bf16_lo(v10, v11); }
        g_Bfrag[idx] = (u64t)r0 | ((u64t)r1 << 32);
    }
    if (idx < 1048576) {   // W_ih B-frags (xproj)
        int lane = idx & 31;
        int kt   = (idx >> 5) & 63;
        int nt2  = idx >> 11;
        int g = lane >> 2, tig = lane & 3;
        int n = nt2 * 8 + g;
        int k0 = kt * 16 + 2 * tig;
        const float* W = Wih + (size_t)n * DTn;
        float a = W[k0], b = W[k0 + 1], c = W[k0 + 8], d = W[k0 + 9];
        g_wfh[idx] = make_uint2(pack_bf16_hi(a, b), pack_bf16_hi(c, d));
        g_wfl[idx] = make_uint2(pack_bf16_lo(a, b), pack_bf16_lo(c, d));
    }
}

// ---------------- x -> A-fragment hi/lo bf16 (one-time) ----------------
__global__ void xprep_kernel(const float* __restrict__ x) {
    int idx = blockIdx.x * blockDim.x + threadIdx.x;   // 0 .. 4194303
    int lane = idx & 31;
    int kt = (idx >> 5) & 63;
    int mt = idx >> 11;
    int g = lane >> 2, tig = lane & 3;
    int m0 = mt * 16 + g;
    int m1 = m0 + 8;
    int k0 = kt * 16 + 2 * tig;
    const float* r0 = x + ((size_t)((m0 & 127) * 256 + (m0 >> 7))) * Hn;
    const float* r1 = x + ((size_t)((m1 & 127) * 256 + (m1 >> 7))) * Hn;
    float2 v00 = *(const float2*)(r0 + k0);
    float2 v01 = *(const float2*)(r0 + k0 + 8);
    float2 v10 = *(const float2*)(r1 + k0);
    float2 v11 = *(const float2*)(r1 + k0 + 8);
    g_xh[idx] = make_uint4(pack_bf16_hi(v00.x, v00.y), pack_bf16_hi(v10.x, v10.y),
                           pack_bf16_hi(v01.x, v01.y), pack_bf16_hi(v11.x, v11.y));
    g_xl[idx] = make_uint4(pack_bf16_lo(v00.x, v00.y), pack_bf16_lo(v10.x, v10.y),
                           pack_bf16_lo(v01.x, v01.y), pack_bf16_lo(v11.x, v11.y));
}

// ---------------- phase 1: x-projection via HMMA bf16 3-split (unchanged from R8) ----------------
__global__ __launch_bounds__(256) void xproj_kernel(
    const float* __restrict__ bih, const float* __restrict__ bhh)
{
    const int tid = threadIdx.x;
    const int wid = tid >> 5, lane = tid & 31;
    const int g = lane >> 2, tig = lane & 3;
    const int wm = wid & 1, wn = wid >> 1;
    const int mt0 = blockIdx.y * 8 + wm * 4;
    const int nt0 = blockIdx.x * 16 + wn * 4;

    const uint4* Ah = g_xh + (size_t)mt0 * 2048 + lane;
    const uint4* Al = g_xl + (size_t)mt0 * 2048 + lane;
    const uint2* Bh = g_wfh + (size_t)nt0 * 2048 + lane;
    const uint2* Bl = g_wfl + (size_t)nt0 * 2048 + lane;

    float dacc[4][4][4];
#pragma unroll
    for (int i = 0; i < 4; i++)
#pragma unroll
        for (int j = 0; j < 4; j++)
#pragma unroll
            for (int e = 0; e < 4; e++) dacc[i][j][e] = 0.f;

    uint4 ah[4], al[4]; uint2 bh[4], bl[4];
#pragma unroll
    for (int i = 0; i < 4; i++) { ah[i] = __ldg(Ah + i * 2048); al[i] = __ldg(Al + i * 2048); }
#pragma unroll
    for (int j = 0; j < 4; j++) { bh[j] = __ldg(Bh + j * 2048); bl[j] = __ldg(Bl + j * 2048); }

    for (int kt = 0; kt < 64; kt++) {
        uint4 ahn[4], aln[4]; uint2 bhn[4], bln[4];
        if (kt < 63) {
#pragma unroll
            for (int i = 0; i < 4; i++) {
                ahn[i] = __ldg(Ah + i * 2048 + (kt + 1) * 32);
                aln[i] = __ldg(Al + i * 2048 + (kt + 1) * 32);
            }
#pragma unroll
            for (int j = 0; j < 4; j++) {
                bhn[j] = __ldg(Bh + j * 2048 + (kt + 1) * 32);
                bln[j] = __ldg(Bl + j * 2048 + (kt + 1) * 32);
            }
        }
#pragma unroll
        for (int i = 0; i < 4; i++)
#pragma unroll
            for (int j = 0; j < 4; j++)
                mma_bf16(dacc[i][j], ah[i].x, ah[i].y, ah[i].z, ah[i].w, bh[j].x, bh[j].y);
#pragma unroll
        for (int i = 0; i < 4; i++)
#pragma unroll
            for (int j = 0; j < 4; j++)
                mma_bf16(dacc[i][j], al[i].x, al[i].y, al[i].z, al[i].w, bh[j].x, bh[j].y);
#pragma unroll
        for (int i = 0; i < 4; i++)
#pragma unroll
            for (int j = 0; j < 4; j++)
                mma_bf16(dacc[i][j], ah[i].x, ah[i].y, ah[i].z, ah[i].w, bl[j].x, bl[j].y);
#pragma unroll
        for (int i = 0; i < 4; i++) { ah[i] = ahn[i]; al[i] = aln[i]; }
#pragma unroll
        for (int j = 0; j < 4; j++) { bh[j] = bhn[j]; bl[j] = bln[j]; }
    }

#pragma unroll
    for (int j = 0; j < 4; j++) {
        int n = (nt0 + j) * 8 + 2 * tig;
        float b0 = bih[n] + bhh[n];
        float b1 = bih[n + 1] + bhh[n + 1];
#pragma unroll
        for (int i = 0; i < 4; i++) {
            int m = (mt0 + i) * 16 + g;
            *(float2*)(g_G + (size_t)m * G4n + n) =
                make_float2(dacc[i][j][0] + b0, dacc[i][j][1] + b1);
            *(float2*)(g_G + (size_t)(m + 8) * G4n + n) =
                make_float2(dacc[i][j][2] + b0, dacc[i][j][3] + b1);
        }
    }
}

// ---------------- GEMM slice: R8's proven body, constant trip count ----------------
template<int KCNT>
__device__ __forceinline__ void gemm_part(float (*dacc)[4],
    const uint4* __restrict__ Ah4, const uint4* __restrict__ Al4,
    const uint2* __restrict__ Bh, const uint2* __restrict__ Bl,
    int ktbase, int lane)
{
    uint4 ahs[3], als[3];
#pragma unroll
    for (int d = 0; d < 3; d++) {
        ahs[d] = __ldcg(Ah4 + d * 32);
        als[d] = __ldcg(Al4 + d * 32);
    }
#pragma unroll
    for (int ktl = 0; ktl < KCNT; ktl++) {
        const int sl = ktl % 3;
        uint4 ah = ahs[sl], al = als[sl];
        if (ktl + 3 < KCNT) {
            ahs[sl] = __ldcg(Ah4 + (ktl + 3) * 32);
            als[sl] = __ldcg(Al4 + (ktl + 3) * 32);
        }
        const int kt = ktbase + ktl;
        uint2 b0 = Bh[(0 * 64 + kt) * 32 + lane];
        uint2 b1r = Bh[(1 * 64 + kt) * 32 + lane];
        uint2 b2r = Bh[(2 * 64 + kt) * 32 + lane];
        uint2 b3 = Bh[(3 * 64 + kt) * 32 + lane];
        mma_bf16(dacc[0], ah.x, ah.y, ah.z, ah.w, b0.x, b0.y);
        mma_bf16(dacc[1], ah.x, ah.y, ah.z, ah.w, b1r.x, b1r.y);
        mma_bf16(dacc[2], ah.x, ah.y, ah.z, ah.w, b2r.x, b2r.y);
        mma_bf16(dacc[3], ah.x, ah.y, ah.z, ah.w, b3.x, b3.y);
        mma_bf16(dacc[0], al.x, al.y, al.z, al.w, b0.x, b0.y);
        mma_bf16(dacc[1], al.x, al.y, al.z, al.w, b1r.x, b1r.y);
        mma_bf16(dacc[2], al.x, al.y, al.z, al.w, b2r.x, b2r.y);
        mma_bf16(dacc[3], al.x, al.y, al.z, al.w, b3.x, b3.y);
        b0 = Bl[(0 * 64 + kt) * 32 + lane];
        b1r = Bl[(1 * 64 + kt) * 32 + lane];
        b2r = Bl[(2 * 64 + kt) * 32 + lane];
        b3 = Bl[(3 * 64 + kt) * 32 + lane];
        mma_bf16(dacc[0], ah.x, ah.y, ah.z, ah.w, b0.x, b0.y);
        mma_bf16(dacc[1], ah.x, ah.y, ah.z, ah.w, b1r.x, b1r.y);
        mma_bf16(dacc[2], ah.x, ah.y, ah.z, ah.w, b2r.x, b2r.y);
        mma_bf16(dacc[3], ah.x, ah.y, ah.z, ah.w, b3.x, b3.y);
    }
}

// ---------------- persistent loop: R8 base + warp-specialized logits on wk1 ----------------
#define LOOP_SMEM 148480
#define KT0 40   // wk0 k-tiles
#define KT1 24   // wk1 k-tiles (wk1 also runs logits)

__global__ __launch_bounds__(512, 1) void loop_kernel(
    const float* __restrict__ Wout, const float* __restrict__ bout,
    const int* __restrict__ tags, const int* __restrict__ mask,
    float* __restrict__ out)
{
    extern __shared__ __align__(16) unsigned char smem[];
    float* red = (float*)smem;
    const uint2* Bh = (const uint2*)(smem + 1024);
    const uint2* Bl = (const uint2*)(smem + 1024 + 65536);
    float* red2 = (float*)(smem + 132096);   // [16][256]

    const int bid = blockIdx.x;
    const int tid = threadIdx.x;
    const int wid = tid >> 5;
    const int lane = tid & 31;
    const int g = lane >> 2, tig = lane & 3;
    const int wk = wid >> 3;
    const int wm = wid & 7;
    const int gtid = tid & 255;

    {
        const uint4* src = (const uint4*)g_Bfrag + (size_t)bid * 8192;
        uint4* dst = (uint4*)(smem + 1024);
        for (int u = tid; u < 8192; u += 512) dst[u] = src[u];
    }
    __syncthreads();

    const int b1 = wm * 16 + g;
    const int b2 = b1 + 8;
    const int kkg0 = bid * 8 + 2 * tig;
    const int ktbase = wk ? KT0 : 0;

    float creg[2][2] = {{0.f, 0.f}, {0.f, 0.f}};
    double lossAcc = 0.0;

    // logits for step ls (h(ls) lives in g_h[(ls&1)^1] == g_h[(ls+1)&1]); wk1 threads only.
    auto do_logits = [&](int ls, bool feed) {
        const float4* h4 = (const float4*)(g_h[(ls + 1) & 1] + bid * Hn);
        float4 hvv = __ldcg(h4 + gtid);
        const float4* W4 = (const float4*)Wout;
        float p[Tn];
#pragma unroll
        for (int t = 0; t < Tn; t++) {
            float4 w = __ldg(W4 + t * 256 + gtid);
            p[t] = hvv.x * w.x + hvv.y * w.y + hvv.z * w.z + hvv.w * w.w;
        }
#pragma unroll
        for (int t = 0; t < Tn; t++) {
#pragma unroll
            for (int o = 16; o > 0; o >>= 1)
                p[t] += __shfl_xor_sync(0xffffffffu, p[t], o);
        }
        if (lane == 0) {
#pragma unroll
            for (int t = 0; t < Tn; t++) red[(gtid >> 5) * Tn + t] = p[t];
        }
        asm volatile("bar.sync 1, 256;" ::: "memory");
        if (gtid < 32) {
            float l = -3.402823466e38f;
            if (gtid < Tn) {
                l = bout[gtid];
#pragma unroll
                for (int w = 0; w < 8; w++) l += red[w * Tn + gtid];
            }
            float v = l; int idx = gtid;
#pragma unroll
            for (int o = 16; o > 0; o >>= 1) {
                float v2 = __shfl_xor_sync(0xffffffffu, v, o);
                int   i2 = __shfl_xor_sync(0xffffffffu, idx, o);
                if (v2 > v || (v2 == v && i2 < idx)) { v = v2; idx = i2; }
            }
            if (feed && gtid == 0) g_ptag[bid] = idx;
            if (mask[bid * Sn + ls] != 0) {
                float e = (gtid < Tn) ? expf(l - v) : 0.f;
#pragma unroll
                for (int o = 16; o > 0; o >>= 1)
                    e += __shfl_xor_sync(0xffffffffu, e, o);
                int y = tags[bid * Sn + ls];
                float ly = __shfl_sync(0xffffffffu, l, y);
                if (gtid == 0) lossAcc += (double)(v + logf(e) - ly);
            }
            if (feed && gtid == 0) {
                __threadfence();
                atomicAdd(&g_ptag_ready, 1u);
            }
        }
    };

    for (int s = 0; s < Sn; s++) {
        float2 Gv[2][4];
        if (tid < 256) {
#pragma unroll
            for (int r2 = 0; r2 < 2; r2++) {
                int r = r2 ? b2 : b1;
                const float* Gp = g_G + (size_t)(s * Bn + r) * G4n + kkg0;
#pragma unroll
                for (int nt = 0; nt < 4; nt++)
                    Gv[r2][nt] = __ldcs((const float2*)(Gp + nt * 1024));
            }
        }

        float dacc[4][4];
#pragma unroll
        for (int nt = 0; nt < 4; nt++)
#pragma unroll
            for (int e = 0; e < 4; e++) dacc[nt][e] = 0.f;

        if (s > 0) {
            // wk1: logits(s-1) first (overlaps wk0's longer GEMM), then its GEMM slice
            if (wk == 1) do_logits(s - 1, true);

            const int par = s & 1;
            const uint4* Ah4 = (const uint4*)g_hAh[par] + (wm * 2048 + ktbase * 32 + lane);
            const uint4* Al4 = (const uint4*)g_hAl[par] + (wm * 2048 + ktbase * 32 + lane);
            if (wk == 0) gemm_part<KT0>(dacc, Ah4, Al4, Bh, Bl, 0, lane);
            else         gemm_part<KT1>(dacc, Ah4, Al4, Bh, Bl, KT0, lane);
        }

        // split-K: wk1 publishes, threads 0-255 accumulate
        if (wk == 1) {
#pragma unroll
            for (int nt = 0; nt < 4; nt++)
#pragma unroll
                for (int e = 0; e < 4; e++)
                    red2[(nt * 4 + e) * 256 + gtid] = dacc[nt][e];
        }
        __syncthreads();
        if (tid < 256) {
#pragma unroll
            for (int nt = 0; nt < 4; nt++)
#pragma unroll
                for (int e = 0; e < 4; e++)
                    dacc[nt][e] += red2[(nt * 4 + e) * 256 + tid];
        }

        if (s > 0) {
            if (tid == 0) {
                while (*(volatile unsigned*)&g_ptag_ready < (unsigned)s * 128u) {}
            }
            __syncthreads();
        }

        // ---- epilogue (threads 0-255) ----
        const int po = (s & 1) ^ 1;
        if (tid < 256) {
            int pt1 = __ldcg(&g_ptag[b1]);
            int pt2 = __ldcg(&g_ptag[b2]);
            const float* W1 = g_Wtag + pt1 * G4n + kkg0;
            const float* W2 = g_Wtag + pt2 * G4n + kkg0;
#pragma unroll
            for (int r2 = 0; r2 < 2; r2++) {
                int r = r2 ? b2 : b1;
                const float* Wt = r2 ? W2 : W1;
                float h01[2];
#pragma unroll
                for (int e = 0; e < 2; e++) {
                    int de = r2 * 2 + e;
                    float G0 = e ? Gv[r2][0].y : Gv[r2][0].x;
                    float G1 = e ? Gv[r2][1].y : Gv[r2][1].x;
                    float G2 = e ? Gv[r2][2].y : Gv[r2][2].x;
                    float G3 = e ? Gv[r2][3].y : Gv[r2][3].x;
                    float gi = dacc[0][de] + G0 + Wt[e];
                    float gf = dacc[1][de] + G1 + Wt[1024 + e];
                    float gg = dacc[2][de] + G2 + Wt[2048 + e];
                    float go = dacc[3][de] + G3 + Wt[3072 + e];
                    gi = 1.f / (1.f + __expf(-gi));
                    gf = 1.f / (1.f + __expf(-gf));
                    gg = tanhf(gg);
                    go = 1.f / (1.f + __expf(-go));
                    creg[r2][e] = gf * creg[r2][e] + gi * gg;
                    h01[e] = go * tanhf(creg[r2][e]);
                }
                *(float2*)(g_h[po] + r * Hn + kkg0) = make_float2(h01[0], h01[1]);
                int idx = ((r >> 4) * 8192) + ((bid >> 1) * 128)
                        + (((r & 7) * 4 + tig) * 4) + ((r >> 3) & 1) + 2 * (bid & 1);
                g_hAh[po][idx] = pack_bf16_hi(h01[0], h01[1]);
                g_hAl[po][idx] = pack_bf16_lo(h01[0], h01[1]);
            }
        }
        grid_bar();
    }

    // tail: logits(255) (loss only; h(255) visible after final grid_bar)
    if (wk == 1) do_logits(255, false);
    if (tid == 256) atomicAdd(&g_loss, lossAcc);
    grid_bar();
    if (bid == 0 && tid == 0) out[0] = (float)(*(volatile double*)&g_loss);
}

// ---------------- launch ----------------
extern "C" void kernel_launch(void* const* d_in, const int* in_sizes, int n_in,
                              void* d_out, int out_size)
{
    const float *x = nullptr, *Wih = nullptr, *Whh = nullptr;
    const float *bih = nullptr, *bhh = nullptr, *Wout = nullptr, *bout = nullptr;
    const int *tags = nullptr, *maskp = nullptr;
    for (int i = 0; i < n_in; i++) {
        int sz = in_sizes[i];
        const void* p = d_in[i];
        switch (sz) {
            case 33554432: x = (const float*)p; break;
            case 4276224:  Wih = (const float*)p; break;
            case 4194304:  Whh = (const float*)p; break;
            case 4096:     if (!bih) bih = (const float*)p; else bhh = (const float*)p; break;
            case 32768:    if (!tags) tags = (const int*)p; else maskp = (const int*)p; break;
            case 20480:    Wout = (const float*)p; break;
            case 20:       bout = (const float*)p; break;
            default: break;
        }
    }

    cudaFuncSetAttribute(loop_kernel, cudaFuncAttributeMaxDynamicSharedMemorySize, LOOP_SMEM);

    init_kernel<<<16384, 256>>>(Wih, Whh);                               // #1
    xprep_kernel<<<16384, 256>>>(x);                                     // #2
    xproj_kernel<<<dim3(32, 256), 256>>>(bih, bhh);                      // #3
    loop_kernel<<<NBLK, 512, LOOP_SMEM>>>(Wout, bout, tags, maskp, (float*)d_out);  // #4 (profiled)
}